// round 10
// baseline (speedup 1.0000x reference)
#include <cuda_runtime.h>
#include <math.h>

#define B_    64
#define S_    512
#define EMB_  512
#define HID_  1024
#define NCTA  128
#define NC    8          // output columns per CTA
#define TPB   512        // 16 warps; warp kg owns k-rows [kg*64, kg*64+64)
#define NW    16

// SMEM floats: 3 plain weight arrays (3*8192) + reduction scratch (16384) = 40960 floats
#define WSZ        8192          // floats per weight array [HID_][NC]
#define RED_OFF    24576
#define SMEM_BYTES (40960 * 4)   // 163840 B -> 1 CTA/SM

// -------- scratch (static device globals; no allocation) --------
__device__ float g_pre1[(size_t)S_ * HID_ * B_];   // [t][n][b]
__device__ float g_H1[2][HID_ * B_];               // [parity][k][m]
__device__ float g_H2[2][HID_ * B_];
__device__ unsigned g_flags[NCTA];                 // per-CTA monotonic barrier flags

// -------- grid barrier: flag array, parallel arrival (no atomic serialization) ----
__device__ __forceinline__ unsigned ld_acq(const unsigned* p) {
    unsigned v;
    asm volatile("ld.acquire.gpu.u32 %0, [%1];" : "=r"(v) : "l"(p) : "memory");
    return v;
}
__device__ __forceinline__ void grid_barrier(int c, unsigned target) {
    __syncthreads();
    if (threadIdx.x == 0) {
        __threadfence();   // block writes (ordered via syncthreads) -> visible before flag
        asm volatile("st.release.gpu.u32 [%0], %1;"
                     :: "l"(&g_flags[c]), "r"(target) : "memory");
    }
    if (threadIdx.x < NCTA) {
        while ((int)(ld_acq(&g_flags[threadIdx.x]) - target) < 0) { __nanosleep(20); }
    }
    __syncthreads();
}

// packed fp32x2 FMA
__device__ __forceinline__ void ffma2(unsigned long long& a,
                                      unsigned long long x,
                                      unsigned long long w) {
    asm("fma.rn.f32x2 %0, %1, %2, %0;" : "+l"(a) : "l"(x), "l"(w));
}
__device__ __forceinline__ unsigned long long dup2(float w) {
    unsigned u = __float_as_uint(w);
    unsigned long long r;
    asm("mov.b64 %0, {%1, %1};" : "=l"(r) : "r"(u));
    return r;
}
struct u64x2 { unsigned long long x, y; };
__device__ __forceinline__ u64x2 ldcg16(const float* p) {
    double2 v = __ldcg((const double2*)p);
    u64x2 r;
    r.x = (unsigned long long)__double_as_longlong(v.x);
    r.y = (unsigned long long)__double_as_longlong(v.y);
    return r;
}

// ================= precompute: pre1[t][n][b] = emb[x[b][t]] @ Wi1 + b1 =================
__global__ __launch_bounds__(256) void pre_kernel(
    const int* __restrict__ x, const float* __restrict__ emb,
    const float* __restrict__ Wi1, const float* __restrict__ b1)
{
    __shared__ int   tok[64];
    __shared__ float As[32 * 68];
    __shared__ float Bs[32 * 64];
    const int tid = threadIdx.x;
    const int t   = blockIdx.y;
    const int n0  = blockIdx.x * 64;

    if (tid < 64) tok[tid] = x[tid * S_ + t];
    __syncthreads();

    const int ty = tid >> 4, tx = tid & 15;
    float4 acc0 = {0,0,0,0}, acc1 = {0,0,0,0}, acc2 = {0,0,0,0}, acc3 = {0,0,0,0};

    const int b_l = tid >> 2, kq = tid & 3;
    for (int kt = 0; kt < 16; ++kt) {
        __syncthreads();
        #pragma unroll
        for (int j = 0; j < 2; ++j) {
            int k4 = kq * 4 + j * 16;
            float4 v = *(const float4*)&emb[(size_t)tok[b_l] * EMB_ + kt * 32 + k4];
            As[(k4+0)*68 + b_l] = v.x;
            As[(k4+1)*68 + b_l] = v.y;
            As[(k4+2)*68 + b_l] = v.z;
            As[(k4+3)*68 + b_l] = v.w;
        }
        #pragma unroll
        for (int j = 0; j < 2; ++j) {
            int kl = (tid >> 4) + j * 16;
            int nq = tid & 15;
            *(float4*)&Bs[kl*64 + nq*4] =
                *(const float4*)&Wi1[(size_t)(kt*32 + kl) * HID_ + n0 + nq*4];
        }
        __syncthreads();
        #pragma unroll
        for (int k = 0; k < 32; ++k) {
            float4 av = *(const float4*)&As[k*68 + ty*4];
            float4 bv = *(const float4*)&Bs[k*64 + tx*4];
            acc0.x += av.x*bv.x; acc0.y += av.x*bv.y; acc0.z += av.x*bv.z; acc0.w += av.x*bv.w;
            acc1.x += av.y*bv.x; acc1.y += av.y*bv.y; acc1.z += av.y*bv.z; acc1.w += av.y*bv.w;
            acc2.x += av.z*bv.x; acc2.y += av.z*bv.y; acc2.z += av.z*bv.z; acc2.w += av.z*bv.w;
            acc3.x += av.w*bv.x; acc3.y += av.w*bv.y; acc3.z += av.w*bv.z; acc3.w += av.w*bv.w;
        }
    }
    float4 b1v = *(const float4*)&b1[n0 + tx*4];
    acc0.x += b1v.x; acc0.y += b1v.y; acc0.z += b1v.z; acc0.w += b1v.w;
    acc1.x += b1v.x; acc1.y += b1v.y; acc1.z += b1v.z; acc1.w += b1v.w;
    acc2.x += b1v.x; acc2.y += b1v.y; acc2.z += b1v.z; acc2.w += b1v.w;
    acc3.x += b1v.x; acc3.y += b1v.y; acc3.z += b1v.z; acc3.w += b1v.w;

    float* outp = &g_pre1[(size_t)t * (HID_*B_)];
    float4 c;
    c = make_float4(acc0.x, acc1.x, acc2.x, acc3.x);
    *(float4*)&outp[(n0+tx*4+0)*B_ + ty*4] = c;
    c = make_float4(acc0.y, acc1.y, acc2.y, acc3.y);
    *(float4*)&outp[(n0+tx*4+1)*B_ + ty*4] = c;
    c = make_float4(acc0.z, acc1.z, acc2.z, acc3.z);
    *(float4*)&outp[(n0+tx*4+2)*B_ + ty*4] = c;
    c = make_float4(acc0.w, acc1.w, acc2.w, acc3.w);
    *(float4*)&outp[(n0+tx*4+3)*B_ + ty*4] = c;
}

// ================= persistent recurrent kernel =================
// 16 warps. Warp kg owns k-rows [kg*64, kg*64+64). Lane (cp,q): cols c0..c0+3,
// batch rows m4..m4+3. h read from L2 (ldcg); weights plain [k][8] in smem.
// Per phase: 16-way partials -> smem; DISTRIBUTED finalize: warp j (0..3)
// reduces h1 col-offset j, warp 4+j reduces h2 col-offset j. Flag-array barrier.
__global__ void __launch_bounds__(TPB, 1) recur_kernel(
    const float* __restrict__ Wh1, const float* __restrict__ Wi2,
    const float* __restrict__ Wh2, const float* __restrict__ b2,
    const float* __restrict__ Wd,  const float* __restrict__ bd,
    float* __restrict__ out)
{
    extern __shared__ float sm[];
    float* Ws1 = sm;                 // [HID_][8]
    float* Wsi = sm + WSZ;
    float* Ws2 = sm + 2 * WSZ;
    float* red = sm + RED_OFF;       // 16384 floats scratch

    const int tid  = threadIdx.x;
    const int c    = blockIdx.x;
    const int kg   = tid >> 5;           // warp = k-group 0..15
    const int lane = tid & 31;
    const int cp   = lane >> 4;          // col-quad 0..1
    const int q    = lane & 15;          // m-quad 0..15
    const int m4   = q * 4;
    const int c0   = c * NC + cp * 4;

    const unsigned bar_base = g_flags[c];   // equal across CTAs between graph replays
    unsigned nbar = 0;

    // fill plain weight slices [k][8]
    for (int e = tid; e < HID_ * 2; e += TPB) {
        int k = e >> 1, h4 = (e & 1) * 4;
        int col = c * NC + h4;
        float4 v;
        v.x = Wh1[(size_t)k * HID_ + col];     v.y = Wh1[(size_t)k * HID_ + col + 1];
        v.z = Wh1[(size_t)k * HID_ + col + 2]; v.w = Wh1[(size_t)k * HID_ + col + 3];
        *(float4*)&Ws1[k * 8 + h4] = v;
        v.x = Wi2[(size_t)k * HID_ + col];     v.y = Wi2[(size_t)k * HID_ + col + 1];
        v.z = Wi2[(size_t)k * HID_ + col + 2]; v.w = Wi2[(size_t)k * HID_ + col + 3];
        *(float4*)&Wsi[k * 8 + h4] = v;
        v.x = Wh2[(size_t)k * HID_ + col];     v.y = Wh2[(size_t)k * HID_ + col + 1];
        v.z = Wh2[(size_t)k * HID_ + col + 2]; v.w = Wh2[(size_t)k * HID_ + col + 3];
        *(float4*)&Ws2[k * 8 + h4] = v;
    }
    if (tid < 128) {
        float4 z = {0,0,0,0};
        *(float4*)&g_H1[0][c * NC * B_ + tid * 4] = z;
        *(float4*)&g_H2[0][c * NC * B_ + tid * 4] = z;
    }
    // scalar b2 for the h2-reducing warps (kg 4..7): col = c*NC + cp*4 + (kg-4)
    const float b2s = b2[c * NC + cp * 4 + (kg & 3)];
    grid_barrier(c, bar_base + (++nbar));

    for (int p = 0; p <= S_; ++p) {
        const int pr = p & 1;
        const float* H1r = g_H1[pr] + (kg << 6) * B_ + m4;    // h1(p), warp k-slice
        const float* H2r = g_H2[pr ^ 1] + (kg << 6) * B_ + m4;

        unsigned long long a1[4][2], a2[4][2];
        #pragma unroll
        for (int ci = 0; ci < 4; ++ci) {
            a1[ci][0] = a1[ci][1] = 0ull;
            a2[ci][0] = a2[ci][1] = 0ull;
        }
        if (kg == 0 && p < S_) {         // seed a1 with pre1 (this thread's tile)
            const float* pp = &g_pre1[(size_t)p * (HID_ * B_)];
            #pragma unroll
            for (int ci = 0; ci < 4; ++ci) {
                ulonglong2 v = *(const ulonglong2*)&pp[(c0 + ci) * B_ + m4];
                a1[ci][0] = v.x; a1[ci][1] = v.y;
            }
        }

        const float* w1p = Ws1 + (kg << 6) * 8 + cp * 4;
        const float* wip = Wsi + (kg << 6) * 8 + cp * 4;
        const float* w2p = Ws2 + (kg << 6) * 8 + cp * 4;

        #pragma unroll 8
        for (int kk = 0; kk < 64; ++kk) {
            u64x2 h1 = ldcg16(H1r + kk * B_);
            u64x2 h2 = ldcg16(H2r + kk * B_);
            float4 w1 = *(const float4*)&w1p[kk * 8];
            float4 wi = *(const float4*)&wip[kk * 8];
            float4 w2 = *(const float4*)&w2p[kk * 8];
            const float w1a[4] = {w1.x, w1.y, w1.z, w1.w};
            const float wia[4] = {wi.x, wi.y, wi.z, wi.w};
            const float w2a[4] = {w2.x, w2.y, w2.z, w2.w};
            #pragma unroll
            for (int ci = 0; ci < 4; ++ci) {
                unsigned long long w1d = dup2(w1a[ci]);
                unsigned long long wid = dup2(wia[ci]);
                unsigned long long w2d = dup2(w2a[ci]);
                ffma2(a1[ci][0], h1.x, w1d);
                ffma2(a1[ci][1], h1.y, w1d);
                ffma2(a2[ci][0], h1.x, wid);
                ffma2(a2[ci][1], h1.y, wid);
                ffma2(a2[ci][0], h2.x, w2d);
                ffma2(a2[ci][1], h2.y, w2d);
            }
        }

        // partials -> smem: A1 floats [0,8192), A2 [8192,16384)
        {
            int off = (kg * 32 + lane) * 16;
            ulonglong2 u;
            u.x = a1[0][0]; u.y = a1[0][1]; *(ulonglong2*)&red[off]      = u;
            u.x = a1[1][0]; u.y = a1[1][1]; *(ulonglong2*)&red[off + 4]  = u;
            u.x = a1[2][0]; u.y = a1[2][1]; *(ulonglong2*)&red[off + 8]  = u;
            u.x = a1[3][0]; u.y = a1[3][1]; *(ulonglong2*)&red[off + 12] = u;
            u.x = a2[0][0]; u.y = a2[0][1]; *(ulonglong2*)&red[8192 + off]      = u;
            u.x = a2[1][0]; u.y = a2[1][1]; *(ulonglong2*)&red[8192 + off + 4]  = u;
            u.x = a2[2][0]; u.y = a2[2][1]; *(ulonglong2*)&red[8192 + off + 8]  = u;
            u.x = a2[3][0]; u.y = a2[3][1]; *(ulonglong2*)&red[8192 + off + 12] = u;
        }
        __syncthreads();

        // distributed finalize: warp j (0..3) -> h1 col j; warp 4+j -> h2 col j.
        // Each thread: 16 LDS.128 + sum + 1 tanh-float4 + 1 STG.128.
        if (kg < 4 && p < S_) {
            const int j = kg;
            float4 f = {0, 0, 0, 0};
            #pragma unroll
            for (int g = 0; g < NW; ++g) {
                float4 v = *(const float4*)&red[(g * 32 + lane) * 16 + j * 4];
                f.x += v.x; f.y += v.y; f.z += v.z; f.w += v.w;
            }
            float4 o = make_float4(tanhf(f.x), tanhf(f.y), tanhf(f.z), tanhf(f.w));
            *(float4*)&g_H1[pr ^ 1][(c0 + j) * B_ + m4] = o;
        }
        if (kg >= 4 && kg < 8 && p > 0) {
            const int j = kg - 4;
            float4 f = {b2s, b2s, b2s, b2s};
            #pragma unroll
            for (int g = 0; g < NW; ++g) {
                float4 v = *(const float4*)&red[8192 + (g * 32 + lane) * 16 + j * 4];
                f.x += v.x; f.y += v.y; f.z += v.z; f.w += v.w;
            }
            float4 o = make_float4(tanhf(f.x), tanhf(f.y), tanhf(f.z), tanhf(f.w));
            *(float4*)&g_H2[pr][(c0 + j) * B_ + m4] = o;
        }
        grid_barrier(c, bar_base + (++nbar));
    }

    // epilogue: out[b] = sigmoid(h2(512) @ Wd + bd); h2(512) at parity 0
    if (c == 0 && tid < 128) {
        const int b = tid >> 1, h = tid & 1;
        const float* H2f = g_H2[0];
        float s = 0.f;
        #pragma unroll 8
        for (int k = h * 512; k < h * 512 + 512; ++k)
            s += __ldcg(&H2f[k * B_ + b]) * Wd[k];
        s += __shfl_xor_sync(0xffffffffu, s, 1);
        if (h == 0) out[b] = 1.f / (1.f + expf(-(s + bd[0])));
    }
}

// ================= launch =================
extern "C" void kernel_launch(void* const* d_in, const int* in_sizes, int n_in,
                              void* d_out, int out_size) {
    const int*   x   = (const int*)  d_in[0];
    const float* emb = (const float*)d_in[1];
    const float* Wi1 = (const float*)d_in[2];
    const float* Wh1 = (const float*)d_in[3];
    const float* b1  = (const float*)d_in[4];
    const float* Wi2 = (const float*)d_in[5];
    const float* Wh2 = (const float*)d_in[6];
    const float* b2  = (const float*)d_in[7];
    const float* Wd  = (const float*)d_in[8];
    const float* bd  = (const float*)d_in[9];
    float* out = (float*)d_out;

    cudaFuncSetAttribute(recur_kernel,
                         cudaFuncAttributeMaxDynamicSharedMemorySize, SMEM_BYTES);

    pre_kernel<<<dim3(16, 512), 256>>>(x, emb, Wi1, b1);
    recur_kernel<<<NCTA, TPB, SMEM_BYTES>>>(Wh1, Wi2, Wh2, b2, Wd, bd, out);
}

// round 13
// speedup vs baseline: 1.3736x; 1.3736x over previous
#include <cuda_runtime.h>
#include <math.h>

#define B_    64
#define S_    512
#define EMB_  512
#define HID_  1024
#define NCTA  128
#define NC    8          // output columns per CTA
#define TPB   512        // 16 warps; warp kg owns k-rows [kg*64, kg*64+64)
#define NW    16

// SMEM floats: 3 plain weight arrays (3*8192) + reduction scratch (16384) = 40960 floats
#define WSZ        8192          // floats per weight array [HID_][NC]
#define RED_OFF    24576
#define SMEM_BYTES (40960 * 4)   // 163840 B -> 1 CTA/SM

// -------- scratch (static device globals; no allocation) --------
__device__ float g_pre1[(size_t)S_ * HID_ * B_];   // [t][n][b]
__device__ float g_H1[2][HID_ * B_];               // [parity][k][m]
__device__ float g_H2[2][HID_ * B_];
__device__ unsigned g_cnt;
__device__ unsigned g_gen;

// -------- grid barrier (proven R6/R8/R9/R10): atomic count + acquire/release gen ----
__device__ __forceinline__ unsigned ld_acq(const unsigned* p) {
    unsigned v;
    asm volatile("ld.acquire.gpu.u32 %0, [%1];" : "=r"(v) : "l"(p) : "memory");
    return v;
}
__device__ __forceinline__ void grid_barrier() {
    __syncthreads();
    if (threadIdx.x == 0) {
        __threadfence();
        unsigned my = ld_acq(&g_gen);
        if (atomicAdd(&g_cnt, 1u) == NCTA - 1) {
            atomicExch(&g_cnt, 0u);
            asm volatile("st.release.gpu.u32 [%0], %1;" :: "l"(&g_gen), "r"(my + 1) : "memory");
        } else {
            while (ld_acq(&g_gen) == my) { __nanosleep(24); }
        }
    }
    __syncthreads();
}

// packed fp32x2 FMA
__device__ __forceinline__ void ffma2(unsigned long long& a,
                                      unsigned long long x,
                                      unsigned long long w) {
    asm("fma.rn.f32x2 %0, %1, %2, %0;" : "+l"(a) : "l"(x), "l"(w));
}
__device__ __forceinline__ unsigned long long dup2(float w) {
    unsigned u = __float_as_uint(w);
    unsigned long long r;
    asm("mov.b64 %0, {%1, %1};" : "=l"(r) : "r"(u));
    return r;
}
struct u64x2 { unsigned long long x, y; };
__device__ __forceinline__ u64x2 ldcg16(const float* p) {
    double2 v = __ldcg((const double2*)p);
    u64x2 r;
    r.x = (unsigned long long)__double_as_longlong(v.x);
    r.y = (unsigned long long)__double_as_longlong(v.y);
    return r;
}

// ================= precompute: pre1[t][n][b] = emb[x[b][t]] @ Wi1 + b1 =================
__global__ __launch_bounds__(256) void pre_kernel(
    const int* __restrict__ x, const float* __restrict__ emb,
    const float* __restrict__ Wi1, const float* __restrict__ b1)
{
    __shared__ int   tok[64];
    __shared__ float As[32 * 68];
    __shared__ float Bs[32 * 64];
    const int tid = threadIdx.x;
    const int t   = blockIdx.y;
    const int n0  = blockIdx.x * 64;

    if (tid < 64) tok[tid] = x[tid * S_ + t];
    __syncthreads();

    const int ty = tid >> 4, tx = tid & 15;
    float4 acc0 = {0,0,0,0}, acc1 = {0,0,0,0}, acc2 = {0,0,0,0}, acc3 = {0,0,0,0};

    const int b_l = tid >> 2, kq = tid & 3;
    for (int kt = 0; kt < 16; ++kt) {
        __syncthreads();
        #pragma unroll
        for (int j = 0; j < 2; ++j) {
            int k4 = kq * 4 + j * 16;
            float4 v = *(const float4*)&emb[(size_t)tok[b_l] * EMB_ + kt * 32 + k4];
            As[(k4+0)*68 + b_l] = v.x;
            As[(k4+1)*68 + b_l] = v.y;
            As[(k4+2)*68 + b_l] = v.z;
            As[(k4+3)*68 + b_l] = v.w;
        }
        #pragma unroll
        for (int j = 0; j < 2; ++j) {
            int kl = (tid >> 4) + j * 16;
            int nq = tid & 15;
            *(float4*)&Bs[kl*64 + nq*4] =
                *(const float4*)&Wi1[(size_t)(kt*32 + kl) * HID_ + n0 + nq*4];
        }
        __syncthreads();
        #pragma unroll
        for (int k = 0; k < 32; ++k) {
            float4 av = *(const float4*)&As[k*68 + ty*4];
            float4 bv = *(const float4*)&Bs[k*64 + tx*4];
            acc0.x += av.x*bv.x; acc0.y += av.x*bv.y; acc0.z += av.x*bv.z; acc0.w += av.x*bv.w;
            acc1.x += av.y*bv.x; acc1.y += av.y*bv.y; acc1.z += av.y*bv.z; acc1.w += av.y*bv.w;
            acc2.x += av.z*bv.x; acc2.y += av.z*bv.y; acc2.z += av.z*bv.z; acc2.w += av.z*bv.w;
            acc3.x += av.w*bv.x; acc3.y += av.w*bv.y; acc3.z += av.w*bv.z; acc3.w += av.w*bv.w;
        }
    }
    float4 b1v = *(const float4*)&b1[n0 + tx*4];
    acc0.x += b1v.x; acc0.y += b1v.y; acc0.z += b1v.z; acc0.w += b1v.w;
    acc1.x += b1v.x; acc1.y += b1v.y; acc1.z += b1v.z; acc1.w += b1v.w;
    acc2.x += b1v.x; acc2.y += b1v.y; acc2.z += b1v.z; acc2.w += b1v.w;
    acc3.x += b1v.x; acc3.y += b1v.y; acc3.z += b1v.z; acc3.w += b1v.w;

    float* outp = &g_pre1[(size_t)t * (HID_*B_)];
    float4 c;
    c = make_float4(acc0.x, acc1.x, acc2.x, acc3.x);
    *(float4*)&outp[(n0+tx*4+0)*B_ + ty*4] = c;
    c = make_float4(acc0.y, acc1.y, acc2.y, acc3.y);
    *(float4*)&outp[(n0+tx*4+1)*B_ + ty*4] = c;
    c = make_float4(acc0.z, acc1.z, acc2.z, acc3.z);
    *(float4*)&outp[(n0+tx*4+2)*B_ + ty*4] = c;
    c = make_float4(acc0.w, acc1.w, acc2.w, acc3.w);
    *(float4*)&outp[(n0+tx*4+3)*B_ + ty*4] = c;
}

// ================= persistent recurrent kernel =================
// 16 warps. Warp kg owns k-rows [kg*64, kg*64+64). Lane (cp,q): cols c0..c0+3,
// batch rows m4..m4+3. h read from L2 (ldcg); weights plain [k][8] in smem.
// Partials stored CONFLICT-FREE: component j of warp kg at
// redA[((j*16+kg)*32+lane)*4] (h1) / redB[...] (h2) -> every STS/LDS warp
// request is 512B contiguous. Distributed finalize: warp j (0..3) -> h1
// col-offset j; warp 4+j -> h2 col-offset j.
__global__ void __launch_bounds__(TPB, 1) recur_kernel(
    const float* __restrict__ Wh1, const float* __restrict__ Wi2,
    const float* __restrict__ Wh2, const float* __restrict__ b2,
    const float* __restrict__ Wd,  const float* __restrict__ bd,
    float* __restrict__ out)
{
    extern __shared__ float sm[];
    float* Ws1  = sm;                 // [HID_][8]
    float* Wsi  = sm + WSZ;
    float* Ws2  = sm + 2 * WSZ;
    float* redA = sm + RED_OFF;       // 8192 floats (h1 partials)
    float* redB = sm + RED_OFF + 8192;// 8192 floats (h2 partials)

    const int tid  = threadIdx.x;
    const int c    = blockIdx.x;
    const int kg   = tid >> 5;           // warp = k-group 0..15
    const int lane = tid & 31;
    const int cp   = lane >> 4;          // col-quad 0..1
    const int q    = lane & 15;          // m-quad 0..15
    const int m4   = q * 4;
    const int c0   = c * NC + cp * 4;

    // fill plain weight slices [k][8]
    for (int k = tid; k < HID_; k += TPB) {
        #pragma unroll
        for (int hh = 0; hh < 2; ++hh) {
            int h4 = hh * 4;
            int col = c * NC + h4;
            float4 v;
            v.x = Wh1[(size_t)k * HID_ + col];     v.y = Wh1[(size_t)k * HID_ + col + 1];
            v.z = Wh1[(size_t)k * HID_ + col + 2]; v.w = Wh1[(size_t)k * HID_ + col + 3];
            *(float4*)&Ws1[k * 8 + h4] = v;
            v.x = Wi2[(size_t)k * HID_ + col];     v.y = Wi2[(size_t)k * HID_ + col + 1];
            v.z = Wi2[(size_t)k * HID_ + col + 2]; v.w = Wi2[(size_t)k * HID_ + col + 3];
            *(float4*)&Wsi[k * 8 + h4] = v;
            v.x = Wh2[(size_t)k * HID_ + col];     v.y = Wh2[(size_t)k * HID_ + col + 1];
            v.z = Wh2[(size_t)k * HID_ + col + 2]; v.w = Wh2[(size_t)k * HID_ + col + 3];
            *(float4*)&Ws2[k * 8 + h4] = v;
        }
    }
    if (tid < 128) {
        float4 z = {0,0,0,0};
        *(float4*)&g_H1[0][c * NC * B_ + tid * 4] = z;
        *(float4*)&g_H2[0][c * NC * B_ + tid * 4] = z;
    }
    // scalar b2 for h2-reducing warps (kg 4..7): col = c*NC + cp*4 + (kg-4)
    const float b2s = b2[c * NC + cp * 4 + (kg & 3)];
    grid_barrier();

    for (int p = 0; p <= S_; ++p) {
        const int pr = p & 1;
        const float* H1r = g_H1[pr] + (kg << 6) * B_ + m4;    // h1(p), warp k-slice
        const float* H2r = g_H2[pr ^ 1] + (kg << 6) * B_ + m4;

        unsigned long long a1[4][2], a2[4][2];
        #pragma unroll
        for (int ci = 0; ci < 4; ++ci) {
            a1[ci][0] = a1[ci][1] = 0ull;
            a2[ci][0] = a2[ci][1] = 0ull;
        }
        if (kg == 0 && p < S_) {         // seed a1 with pre1 (this thread's tile)
            const float* pp = &g_pre1[(size_t)p * (HID_ * B_)];
            #pragma unroll
            for (int ci = 0; ci < 4; ++ci) {
                ulonglong2 v = *(const ulonglong2*)&pp[(c0 + ci) * B_ + m4];
                a1[ci][0] = v.x; a1[ci][1] = v.y;
            }
        }

        const float* w1p = Ws1 + (kg << 6) * 8 + cp * 4;
        const float* wip = Wsi + (kg << 6) * 8 + cp * 4;
        const float* w2p = Ws2 + (kg << 6) * 8 + cp * 4;

        #pragma unroll 8
        for (int kk = 0; kk < 64; ++kk) {
            u64x2 h1 = ldcg16(H1r + kk * B_);
            u64x2 h2 = ldcg16(H2r + kk * B_);
            float4 w1 = *(const float4*)&w1p[kk * 8];
            float4 wi = *(const float4*)&wip[kk * 8];
            float4 w2 = *(const float4*)&w2p[kk * 8];
            const float w1a[4] = {w1.x, w1.y, w1.z, w1.w};
            const float wia[4] = {wi.x, wi.y, wi.z, wi.w};
            const float w2a[4] = {w2.x, w2.y, w2.z, w2.w};
            #pragma unroll
            for (int ci = 0; ci < 4; ++ci) {
                unsigned long long w1d = dup2(w1a[ci]);
                unsigned long long wid = dup2(wia[ci]);
                unsigned long long w2d = dup2(w2a[ci]);
                ffma2(a1[ci][0], h1.x, w1d);
                ffma2(a1[ci][1], h1.y, w1d);
                ffma2(a2[ci][0], h1.x, wid);
                ffma2(a2[ci][1], h1.y, wid);
                ffma2(a2[ci][0], h2.x, w2d);
                ffma2(a2[ci][1], h2.y, w2d);
            }
        }

        // partials -> smem, conflict-free layout:
        //   component j of (kg,lane): redA/redB[((j*16+kg)*32+lane)*4]
        {
            #pragma unroll
            for (int j = 0; j < 4; ++j) {
                ulonglong2 u;
                u.x = a1[j][0]; u.y = a1[j][1];
                *(ulonglong2*)&redA[((j * 16 + kg) * 32 + lane) * 4] = u;
            }
            #pragma unroll
            for (int j = 0; j < 4; ++j) {
                ulonglong2 u;
                u.x = a2[j][0]; u.y = a2[j][1];
                *(ulonglong2*)&redB[((j * 16 + kg) * 32 + lane) * 4] = u;
            }
        }
        __syncthreads();

        // distributed finalize (conflict-free reads): warp j -> h1 col j; warp 4+j -> h2.
        if (kg < 4 && p < S_) {
            const int j = kg;
            float4 f = {0, 0, 0, 0};
            #pragma unroll
            for (int g = 0; g < NW; ++g) {
                float4 v = *(const float4*)&redA[((j * 16 + g) * 32 + lane) * 4];
                f.x += v.x; f.y += v.y; f.z += v.z; f.w += v.w;
            }
            float4 o = make_float4(tanhf(f.x), tanhf(f.y), tanhf(f.z), tanhf(f.w));
            *(float4*)&g_H1[pr ^ 1][(c0 + j) * B_ + m4] = o;
        }
        if (kg >= 4 && kg < 8 && p > 0) {
            const int j = kg - 4;
            float4 f = {b2s, b2s, b2s, b2s};
            #pragma unroll
            for (int g = 0; g < NW; ++g) {
                float4 v = *(const float4*)&redB[((j * 16 + g) * 32 + lane) * 4];
                f.x += v.x; f.y += v.y; f.z += v.z; f.w += v.w;
            }
            float4 o = make_float4(tanhf(f.x), tanhf(f.y), tanhf(f.z), tanhf(f.w));
            *(float4*)&g_H2[pr][(c0 + j) * B_ + m4] = o;
        }
        grid_barrier();
    }

    // epilogue: out[b] = sigmoid(h2(512) @ Wd + bd); h2(512) at parity 0
    if (c == 0 && tid < 128) {
        const int b = tid >> 1, h = tid & 1;
        const float* H2f = g_H2[0];
        float s = 0.f;
        #pragma unroll 8
        for (int k = h * 512; k < h * 512 + 512; ++k)
            s += __ldcg(&H2f[k * B_ + b]) * Wd[k];
        s += __shfl_xor_sync(0xffffffffu, s, 1);
        if (h == 0) out[b] = 1.f / (1.f + expf(-(s + bd[0])));
    }
}

// ================= launch =================
extern "C" void kernel_launch(void* const* d_in, const int* in_sizes, int n_in,
                              void* d_out, int out_size) {
    const int*   x   = (const int*)  d_in[0];
    const float* emb = (const float*)d_in[1];
    const float* Wi1 = (const float*)d_in[2];
    const float* Wh1 = (const float*)d_in[3];
    const float* b1  = (const float*)d_in[4];
    const float* Wi2 = (const float*)d_in[5];
    const float* Wh2 = (const float*)d_in[6];
    const float* b2  = (const float*)d_in[7];
    const float* Wd  = (const float*)d_in[8];
    const float* bd  = (const float*)d_in[9];
    float* out = (float*)d_out;

    cudaFuncSetAttribute(recur_kernel,
                         cudaFuncAttributeMaxDynamicSharedMemorySize, SMEM_BYTES);

    pre_kernel<<<dim3(16, 512), 256>>>(x, emb, Wi1, b1);
    recur_kernel<<<NCTA, TPB, SMEM_BYTES>>>(Wh1, Wi2, Wh2, b2, Wd, bd, out);
}